// round 6
// baseline (speedup 1.0000x reference)
#include <cuda_runtime.h>
#include <math_constants.h>

#define NCLS   20
#define NBOX   400
#define SORTN  512
#define IMGW   1333.0f
#define IMGH   800.0f
#define TOPK   100
#define NSEL   (NCLS * TOPK)     // 2000
#define NW     13                // 400 bits -> 13 u32 words
#define NTILE  13                // 13 x 32 rows = 416 >= 400
#define SENTK  0xFFFFFFFFFFFFFFFFull
#define FULLM  0xFFFFFFFFu
#define NTHR   512

// ---------------- device scratch (counters reset by last block each replay) ----------
__device__ unsigned int       g_mask[NCLS * NBOX * NW];
__device__ unsigned long long g_selkey[NSEL];
__device__ unsigned int       g_maxBits = 0u;
__device__ unsigned int       g_maxCnt  = 0u;
__device__ unsigned int       g_tileCnt[NCLS];
__device__ unsigned int       g_done    = 0u;
__device__ unsigned int       g_T       = 0u;
__device__ unsigned int       g_done2   = 0u;

// descending-sortable mapping (ascending u64 sort -> descending float score)
__device__ __forceinline__ unsigned int ord_desc(float f) {
    unsigned int u = __float_as_uint(f);
    unsigned int m = (u & 0x80000000u) ? ~u : (u | 0x80000000u);
    return ~m;
}
__device__ __forceinline__ float inv_ord(unsigned int o) {
    unsigned int m = ~o;
    unsigned int u = (m & 0x80000000u) ? (m & 0x7FFFFFFFu) : ~m;
    return __uint_as_float(u);
}
__device__ __forceinline__ unsigned long long shfl_xor_u64(unsigned long long v, int jj) {
    unsigned int lo = (unsigned int)v, hi = (unsigned int)(v >> 32);
    lo = __shfl_xor_sync(FULLM, lo, jj);
    hi = __shfl_xor_sync(FULLM, hi, jj);
    return ((unsigned long long)hi << 32) | lo;
}
__device__ __forceinline__ unsigned long long uminll(unsigned long long a, unsigned long long b) { return a < b ? a : b; }
__device__ __forceinline__ unsigned long long umaxll(unsigned long long a, unsigned long long b) { return a > b ? a : b; }

__global__ void __launch_bounds__(NTHR, 2)
k_all(const float* __restrict__ boxes, const float* __restrict__ scores,
      const int* __restrict__ pred_cls, float* __restrict__ out)
{
    // union region: cbox (6.4KB, phases A-D) -> mask (20.8KB, greedy) -> sel (16KB, merge)
    __shared__ __align__(16) unsigned char u_raw[NBOX * NW * 4];   // 20800 B
    __shared__ __align__(16) unsigned long long skey[SORTN];       // 4 KB
    __shared__ __align__(16) float4 s_b[NBOX];                     // 6.4 KB shifted boxes
    __shared__ float        s_a[NBOX];                             // 1.6 KB areas
    __shared__ unsigned int s_wmax[16];
    __shared__ float        s_shift;
    __shared__ int          s_elect, s_r19, s_T;

    float4*             s_cbox = reinterpret_cast<float4*>(u_raw);
    unsigned int*       s_mask = reinterpret_cast<unsigned int*>(u_raw);
    unsigned long long* s_sel  = reinterpret_cast<unsigned long long*>(u_raw);

    const int c    = blockIdx.x / NTILE;      // class
    const int ty   = blockIdx.x - c * NTILE;  // 32-row tile within class
    const int tid  = threadIdx.x;
    const int lane = tid & 31;

    // ---------- phase A: load class, clip, keys, local max ----------
    float lmax = 0.0f;
    bool  valid = false;
    unsigned long long v = SENTK;
    if (tid < NBOX) {
        float4 bx = reinterpret_cast<const float4*>(boxes)[c * NBOX + tid];
        float2 sc = reinterpret_cast<const float2*>(scores)[c * NBOX + tid];
        bool fin = isfinite(bx.x) && isfinite(bx.y) && isfinite(bx.z) && isfinite(bx.w)
                && isfinite(sc.x) && isfinite(sc.y);
        float x1 = fminf(fmaxf(bx.x, 0.0f), IMGW);
        float y1 = fminf(fmaxf(bx.y, 0.0f), IMGH);
        float x2 = fminf(fmaxf(bx.z, 0.0f), IMGW);
        float y2 = fminf(fmaxf(bx.w, 0.0f), IMGH);
        valid = fin && (sc.x > 0.05f);
        float masked = valid ? sc.x : -CUDART_INF_F;
        unsigned int j = (unsigned int)(tid * NCLS + c);   // transposed index
        v = ((unsigned long long)ord_desc(masked) << 32) | j;
        s_cbox[tid] = make_float4(x1, y1, x2, y2);
        lmax = fmaxf(fmaxf(x1, x2), fmaxf(y1, y2));
    }
    unsigned int wb = __reduce_max_sync(FULLM, __float_as_uint(lmax));
    if (lane == 0) s_wmax[tid >> 5] = wb;
    const int m = __syncthreads_count(valid);
    if (ty == 0 && tid == 0) {                 // one publisher per class
        unsigned int mx = 0;
        #pragma unroll
        for (int w = 0; w < 16; w++) mx = max(mx, s_wmax[w]);
        atomicMax(&g_maxBits, mx);
        __threadfence();
        atomicAdd(&g_maxCnt, 1u);
    }

    // ---------- phase B: hybrid bitonic sort of 512 keys (hides the rendezvous) ----------
    for (int k = 2; k <= SORTN; k <<= 1) {
        for (int jj = k >> 1; jj >= 32; jj >>= 1) {
            skey[tid] = v;
            __syncthreads();
            unsigned long long p = skey[tid ^ jj];
            bool km = (((tid & k) == 0) == ((tid & jj) == 0));
            v = km ? uminll(v, p) : umaxll(v, p);
            __syncthreads();
        }
        int j0 = (k >> 1) < 16 ? (k >> 1) : 16;
        for (int jj = j0; jj >= 1; jj >>= 1) {
            unsigned long long p = shfl_xor_u64(v, jj);
            bool km = (((tid & k) == 0) == ((tid & jj) == 0));
            v = km ? uminll(v, p) : umaxll(v, p);
        }
    }
    skey[tid] = v;                             // sorted keys in smem

    // ---------- phase C: wait for global max, compute shift ----------
    if (tid == 0) {
        volatile unsigned int* vc = &g_maxCnt;
        while (*vc < (unsigned)NCLS) { }
        __threadfence();
        unsigned int mv = *(volatile unsigned int*)&g_maxBits;
        s_shift = __fmul_rn((float)c, __fadd_rn(__uint_as_float(mv), 1.0f));
    }
    __syncthreads();

    // ---------- phase D: shifted boxes + areas in sorted order ----------
    const float shift = s_shift;
    if (tid < m) {
        unsigned int j = (unsigned int)skey[tid];
        int b = (int)(j / NCLS);
        float4 bx = s_cbox[b];
        float4 sb = make_float4(__fadd_rn(bx.x, shift), __fadd_rn(bx.y, shift),
                                __fadd_rn(bx.z, shift), __fadd_rn(bx.w, shift));
        s_b[tid] = sb;
        s_a[tid] = __fmul_rn(__fsub_rn(sb.z, sb.x), __fsub_rn(sb.w, sb.y));
    }
    __syncthreads();

    // ---------- phase E: this block's 32-row mask tile ----------
    {
        const int wd = tid >> 5;               // word 0..15 (only <13 used)
        const int i  = ty * 32 + lane;         // row
        if (wd < NW && i < m) {
            unsigned int bits = 0;
            const int lo = wd * 32;
            const int hi = min(m, lo + 32);
            const int st = max(lo, i + 1);
            if (st < hi) {
                float4 bi = s_b[i];
                float  ai = s_a[i];
                for (int jd = st; jd < hi; jd++) {
                    float4 bj = s_b[jd];
                    float iw = fmaxf(__fsub_rn(fminf(bi.z, bj.z), fmaxf(bi.x, bj.x)), 0.0f);
                    float ih = fmaxf(__fsub_rn(fminf(bi.w, bj.w), fmaxf(bi.y, bj.y)), 0.0f);
                    float inter = __fmul_rn(iw, ih);
                    float uni = __fsub_rn(__fadd_rn(ai, s_a[jd]), inter);
                    float iou = (uni > 0.0f) ? __fdiv_rn(inter, uni) : 0.0f;
                    if (iou > 0.5f) bits |= 1u << (jd - lo);
                }
            }
            g_mask[(c * NBOX + i) * NW + wd] = bits;
        }
    }
    __threadfence();
    __syncthreads();
    if (tid == 0) {
        unsigned int r = atomicAdd(&g_tileCnt[c], 1u);
        s_elect = (r == NTILE - 1) ? 1 : 0;    // last tile of this class proceeds
    }
    __syncthreads();
    if (!s_elect) return;

    // ================= elected block (one per class) =================
    __threadfence();                           // acquire peers' mask stores
    for (int t = tid; t < m * NW; t += NTHR) s_mask[t] = g_mask[c * NBOX * NW + t];
    __syncthreads();

    // ---------- greedy scan (warp 0, register-batched) + emit kept top-100 ----------
    if (tid < 32) {
        unsigned int mysup = 0;                // lane w owns rows [32w, 32w+32)
        const int nb = (m + 31) >> 5;
        for (int b = 0; b < nb; b++) {
            unsigned int cur = __shfl_sync(FULLM, mysup, b);
            const int base = b << 5;
            const int rows = min(32, m - base);
            unsigned int wreg[32];
            #pragma unroll
            for (int q = 0; q < 32; q++)
                wreg[q] = (q < rows) ? s_mask[(base + q) * NW + b] : 0u;
            #pragma unroll
            for (int q = 0; q < 32; q++) {
                if (q < rows && !((cur >> q) & 1u)) {
                    cur |= wreg[q];
                    if (lane < NW) mysup |= s_mask[(base + q) * NW + lane];
                }
            }
        }
        int cnt = 0;
        for (int bs = 0; bs < m; bs += 32) {
            int t = bs + lane;
            unsigned int supw = __shfl_sync(FULLM, mysup, t >> 5);
            bool kept = (t < m) && !((supw >> (t & 31)) & 1u);
            unsigned int bal = __ballot_sync(FULLM, kept);
            int pos = cnt + __popc(bal & ((1u << lane) - 1u));
            if (kept && pos < TOPK) g_selkey[c * TOPK + pos] = skey[t];
            cnt += __popc(bal);
        }
        cnt = min(cnt, TOPK);
        for (int p = cnt + lane; p < TOPK; p += 32) g_selkey[c * TOPK + p] = SENTK;
        __threadfence();                       // publish selkey
        __syncwarp();
        if (lane == 0) {
            atomicAdd(&g_T, (unsigned int)cnt);
            __threadfence();
            unsigned int r = atomicAdd(&g_done, 1u);
            s_r19 = (r == NCLS - 1) ? 1 : 0;
        }
    }
    __syncthreads();

    // ---------- wait for all 20 classes' selkey ----------
    if (tid == 0) {
        volatile unsigned int* vd = &g_done;
        while (*vd < (unsigned)NCLS) { }
        __threadfence();
        s_T = (int)*(volatile unsigned int*)&g_T;
    }
    __syncthreads();

    // ---------- load all candidates, rank own class, scatter output ----------
    for (int t = tid; t < NSEL; t += NTHR) s_sel[t] = g_selkey[t];
    __syncthreads();

    const int T = s_T;
    if (s_r19) {                               // one block fills default rows [T, 100)
        for (int r = T + tid; r < TOPK; r += NTHR) {
            out[r * 4 + 0] = 0.0f;
            out[r * 4 + 1] = 0.0f;
            out[r * 4 + 2] = 0.0f;
            out[r * 4 + 3] = 0.0f;
            out[4 * TOPK + r] = 0.0f;
            out[5 * TOPK + r] = -1.0f;
            out[6 * TOPK + r] = 0.0f;
        }
    }

    if (tid < TOPK) {
        unsigned long long e = s_sel[c * TOPK + tid];
        if (e != SENTK) {
            int rank = tid;                    // position within own sorted list
            #pragma unroll
            for (int c2 = 0; c2 < NCLS; c2++) {
                if (c2 == c) continue;
                const unsigned long long* seg = s_sel + c2 * TOPK;
                int lo = 0;                    // lower_bound: #elements < e
                #pragma unroll
                for (int s = 64; s > 0; s >>= 1) {
                    int p = lo + s;
                    if (p <= TOPK && seg[p - 1] < e) lo = p;
                }
                rank += lo;
            }
            if (rank < TOPK) {
                unsigned int j = (unsigned int)e;
                int cc = (int)(j % NCLS);
                int b  = (int)(j / NCLS);
                int i  = cc * NBOX + b;
                float4 bx = reinterpret_cast<const float4*>(boxes)[i];
                out[rank * 4 + 0] = fminf(fmaxf(bx.x, 0.0f), IMGW);
                out[rank * 4 + 1] = fminf(fmaxf(bx.y, 0.0f), IMGH);
                out[rank * 4 + 2] = fminf(fmaxf(bx.z, 0.0f), IMGW);
                out[rank * 4 + 3] = fminf(fmaxf(bx.w, 0.0f), IMGH);
                out[4 * TOPK + rank] = inv_ord((unsigned int)(e >> 32));
                out[5 * TOPK + rank] = (float)pred_cls[i];
                out[6 * TOPK + rank] = 1.0f;
            }
        }
    }

    // ---------- last finisher resets counters for next graph replay ----------
    __syncthreads();
    if (tid == 0) {
        unsigned int r2 = atomicAdd(&g_done2, 1u);
        if (r2 == NCLS - 1) {
            g_maxBits = 0u;
            g_maxCnt  = 0u;
            g_done    = 0u;
            g_T       = 0u;
            g_done2   = 0u;
            #pragma unroll
            for (int c2 = 0; c2 < NCLS; c2++) g_tileCnt[c2] = 0u;
            __threadfence();
        }
    }
}

// ---------------- launch ----------------
extern "C" void kernel_launch(void* const* d_in, const int* in_sizes, int n_in,
                              void* d_out, int out_size) {
    const int*   pred_cls = (const int*)d_in[0];
    const float* boxes    = (const float*)d_in[1];
    const float* scores   = (const float*)d_in[2];
    float* out = (float*)d_out;

    k_all<<<NCLS * NTILE, NTHR>>>(boxes, scores, pred_cls, out);
}